// round 1
// baseline (speedup 1.0000x reference)
#include <cuda_runtime.h>
#include <cuda_fp16.h>
#include <cstdint>

// ---------------------------------------------------------------------------
// Seq2Seq RNN (tanh), B=1024, T=128, H=512, L=4, PRED_LEN=10, IN=OUT=6.
// Strategy: one generic "step" kernel computing
//   out = tanh(X @ Wih^T + bih + H @ Whh^T + bhh)
// as a split-fp16 (hi+lo, 3 products) tensor-core GEMM with fp32 accumulate.
// Encoder: 4 layers x 128 sequential steps (input projection fused into step).
// Decoder: 10 steps x 4 layers. FC head at the end.
// ---------------------------------------------------------------------------

#define BM 64
#define BN 64
#define KBLK 32

// Scratch (device globals; allocation APIs are forbidden).
static __device__ float g_bufA[67108864];        // [1024,128,512]
static __device__ float g_bufB[67108864];        // [1024,128,512]
static __device__ float g_hT0[524288];           // [1024,512] enc layer0 final h
static __device__ float g_hT1[524288];           // [1024,512] enc layer1 final h
static __device__ float g_dh[2 * 4 * 524288];    // decoder hidden ping-pong [2][4][1024,512]
static __device__ float g_decout[5242880];       // [1024,10,512]

__device__ __forceinline__ uint32_t smem_u32(const void* p) {
    return (uint32_t)__cvta_generic_to_shared(p);
}

__device__ __forceinline__ void mma16816(float* c,
                                         uint32_t a0, uint32_t a1, uint32_t a2, uint32_t a3,
                                         uint32_t b0, uint32_t b1) {
    asm volatile(
        "mma.sync.aligned.m16n8k16.row.col.f32.f16.f16.f32 "
        "{%0,%1,%2,%3}, {%4,%5,%6,%7}, {%8,%9}, {%0,%1,%2,%3};"
        : "+f"(c[0]), "+f"(c[1]), "+f"(c[2]), "+f"(c[3])
        : "r"(a0), "r"(a1), "r"(a2), "r"(a3), "r"(b0), "r"(b1));
}

__device__ __forceinline__ void ldsm_x4(uint32_t addr, uint32_t& r0, uint32_t& r1,
                                        uint32_t& r2, uint32_t& r3) {
    asm volatile("ldmatrix.sync.aligned.m8n8.x4.shared.b16 {%0,%1,%2,%3}, [%4];"
                 : "=r"(r0), "=r"(r1), "=r"(r2), "=r"(r3) : "r"(addr));
}

__device__ __forceinline__ void ldsm_x4_t(uint32_t addr, uint32_t& r0, uint32_t& r1,
                                          uint32_t& r2, uint32_t& r3) {
    asm volatile("ldmatrix.sync.aligned.m8n8.x4.trans.shared.b16 {%0,%1,%2,%3}, [%4];"
                 : "=r"(r0), "=r"(r1), "=r"(r2), "=r"(r3) : "r"(addr));
}

// One K=512 pass: acc += split16(A[bm0:bm0+64, :]) @ split16(W[bn0:bn0+64, :])^T
// A is fp32 row-major with leading dim lda; W is fp32 [512 rows=n][512 cols=k].
__device__ __forceinline__ void gemm_pass(
    const float* __restrict__ A, long long lda,
    const float* __restrict__ W,
    int bm0, int bn0, int tid,
    __half (*sAh)[40], __half (*sAl)[40],
    __half (*sBh)[72], __half (*sBl)[72],
    float acc[4][4])
{
    const int lane = tid & 31;
    const int warp = tid >> 5;
    const int wm = (warp & 3) * 16;   // 4 warps along M
    const int wn = (warp >> 2) * 32;  // 2 warps along N
    const int mrow = tid >> 3;        // 0..31
    const int kq = (tid & 7) * 4;     // 0..28

    for (int k0 = 0; k0 < 512; k0 += KBLK) {
        // Stage + split A tile (64 x 32) and B tile (transposed into [k][n]).
#pragma unroll
        for (int r = 0; r < 2; ++r) {
            const int m = mrow + r * 32;
            const float4 v = *reinterpret_cast<const float4*>(
                A + (long long)(bm0 + m) * lda + k0 + kq);
            const float vv[4] = {v.x, v.y, v.z, v.w};
#pragma unroll
            for (int j = 0; j < 4; ++j) {
                const __half hi = __float2half_rn(vv[j]);
                const __half lo = __float2half_rn(vv[j] - __half2float(hi));
                sAh[m][kq + j] = hi;
                sAl[m][kq + j] = lo;
            }
            const int n = m;
            const float4 w = *reinterpret_cast<const float4*>(
                W + (long long)(bn0 + n) * 512 + k0 + kq);
            const float ww[4] = {w.x, w.y, w.z, w.w};
#pragma unroll
            for (int j = 0; j < 4; ++j) {
                const __half hi = __float2half_rn(ww[j]);
                const __half lo = __float2half_rn(ww[j] - __half2float(hi));
                sBh[kq + j][n] = hi;
                sBl[kq + j][n] = lo;
            }
        }
        __syncthreads();

        // 3 split products: Ah*Bh + Al*Bh + Ah*Bl  (Al*Bl dropped: ~2^-22 rel)
#pragma unroll
        for (int combo = 0; combo < 3; ++combo) {
            const __half (*Ap)[40] = (combo == 1) ? sAl : sAh;
            const __half (*Bp)[72] = (combo == 2) ? sBl : sBh;
#pragma unroll
            for (int kk = 0; kk < KBLK; kk += 16) {
                uint32_t a0, a1, a2, a3;
                const uint32_t aaddr =
                    smem_u32(&Ap[wm + (lane & 15)][kk + ((lane >> 4) << 3)]);
                ldsm_x4(aaddr, a0, a1, a2, a3);
#pragma unroll
                for (int pair = 0; pair < 2; ++pair) {
                    const int nb = wn + pair * 16;
                    const uint32_t baddr = smem_u32(
                        &Bp[kk + (lane & 7) + (((lane >> 3) & 1) << 3)]
                           [nb + ((lane >> 4) << 3)]);
                    uint32_t b0, b1, b2, b3;
                    ldsm_x4_t(baddr, b0, b1, b2, b3);
                    mma16816(acc[pair * 2 + 0], a0, a1, a2, a3, b0, b1);
                    mma16816(acc[pair * 2 + 1], a0, a1, a2, a3, b2, b3);
                }
            }
        }
        __syncthreads();
    }
}

// out[m, n] = tanh( X@Wih^T + bih + H@Whh^T + bhh ),  m in [0,1024), n in [0,512)
// k1 == 6   : X is the raw input (direct fp32 path, Wih is [512][6])
// k1 == 512 : X pass is a full GEMM pass
// H == null : hidden term skipped (t == 0)
__global__ void __launch_bounds__(256) step_kernel(
    const float* __restrict__ X, long long ldx, int k1,
    const float* __restrict__ Wih,
    const float* __restrict__ H, long long ldh,
    const float* __restrict__ Whh,
    const float* __restrict__ bih, const float* __restrict__ bhh,
    float* __restrict__ out, long long ldo,
    float* __restrict__ out2, long long ldo2)
{
    __shared__ __half sAh[64][40], sAl[64][40];
    __shared__ __half sBh[32][72], sBl[32][72];

    const int tid = threadIdx.x;
    const int lane = tid & 31;
    const int warp = tid >> 5;
    const int wm = (warp & 3) * 16;
    const int wn = (warp >> 2) * 32;
    const int bm0 = blockIdx.x * BM;
    const int bn0 = blockIdx.y * BN;

    float acc[4][4];
#pragma unroll
    for (int i = 0; i < 4; ++i)
#pragma unroll
        for (int j = 0; j < 4; ++j) acc[i][j] = 0.f;

    if (k1 == 6) {
        // tiny input projection, direct fp32
        const int mlo = bm0 + wm + (lane >> 2);
        float xr[2][6];
#pragma unroll
        for (int r = 0; r < 2; ++r)
#pragma unroll
            for (int k = 0; k < 6; ++k)
                xr[r][k] = X[(long long)(mlo + r * 8) * ldx + k];
#pragma unroll
        for (int nt = 0; nt < 4; ++nt)
#pragma unroll
            for (int j = 0; j < 2; ++j) {
                const int gn = bn0 + wn + nt * 8 + (lane & 3) * 2 + j;
#pragma unroll
                for (int k = 0; k < 6; ++k) {
                    const float w = Wih[gn * 6 + k];
                    acc[nt][j]     += xr[0][k] * w;
                    acc[nt][2 + j] += xr[1][k] * w;
                }
            }
    } else {
        gemm_pass(X, ldx, Wih, bm0, bn0, tid, sAh, sAl, sBh, sBl, acc);
    }
    if (H != nullptr) {
        gemm_pass(H, ldh, Whh, bm0, bn0, tid, sAh, sAl, sBh, sBl, acc);
    }

    // epilogue: bias + tanh + store (optional dual write)
#pragma unroll
    for (int nt = 0; nt < 4; ++nt)
#pragma unroll
        for (int i = 0; i < 2; ++i)
#pragma unroll
            for (int j = 0; j < 2; ++j) {
                const int m = bm0 + wm + (lane >> 2) + i * 8;
                const int gn = bn0 + wn + nt * 8 + (lane & 3) * 2 + j;
                const float v = tanhf(acc[nt][i * 2 + j] + bih[gn] + bhh[gn]);
                out[(long long)m * ldo + gn] = v;
                if (out2) out2[(long long)m * ldo2 + gn] = v;
            }
}

// outputs[r, n] = decout[r, :] @ fcW[n, :] + fcb[n],  r in [0, 10240), n in [0,6)
__global__ void __launch_bounds__(256) fc_kernel(
    const float* __restrict__ in, const float* __restrict__ W,
    const float* __restrict__ b, float* __restrict__ out)
{
    __shared__ float Ws[6 * 512];
    const int tid = threadIdx.x;
    for (int i = tid; i < 6 * 512; i += 256) Ws[i] = W[i];
    __syncthreads();

    const int warp = tid >> 5, lane = tid & 31;
    const int row = blockIdx.x * 8 + warp;
    float p[6] = {0.f, 0.f, 0.f, 0.f, 0.f, 0.f};
    for (int k = lane; k < 512; k += 32) {
        const float v = in[(long long)row * 512 + k];
#pragma unroll
        for (int n = 0; n < 6; ++n) p[n] += v * Ws[n * 512 + k];
    }
#pragma unroll
    for (int off = 16; off > 0; off >>= 1)
#pragma unroll
        for (int n = 0; n < 6; ++n)
            p[n] += __shfl_down_sync(0xffffffffu, p[n], off);
    if (lane == 0) {
#pragma unroll
        for (int n = 0; n < 6; ++n) out[(long long)row * 6 + n] = p[n] + b[n];
    }
}

extern "C" void kernel_launch(void* const* d_in, const int* in_sizes, int n_in,
                              void* d_out, int out_size) {
    const float* x     = (const float*)d_in[0];   // [1024,128,6]
    const float* eWih0 = (const float*)d_in[1];   // [512,6]
    const float* eWih  = (const float*)d_in[2];   // [3,512,512]
    const float* eWhh  = (const float*)d_in[3];   // [4,512,512]
    const float* ebih  = (const float*)d_in[4];   // [4,512]
    const float* ebhh  = (const float*)d_in[5];   // [4,512]
    const float* dWih  = (const float*)d_in[6];   // [4,512,512]
    const float* dWhh  = (const float*)d_in[7];   // [4,512,512]
    const float* dbih  = (const float*)d_in[8];   // [4,512]
    const float* dbhh  = (const float*)d_in[9];   // [4,512]
    const float* fcW   = (const float*)d_in[10];  // [6,512]
    const float* fcb   = (const float*)d_in[11];  // [6]

    float* out = (float*)d_out;
    float* enc_out = out;                          // [1024,128,512]
    float* outputs = out + 67108864LL;             // [1024,10,6]

    float *bufA, *bufB, *hT0, *hT1, *dh, *dec;
    cudaGetSymbolAddress((void**)&bufA, g_bufA);
    cudaGetSymbolAddress((void**)&bufB, g_bufB);
    cudaGetSymbolAddress((void**)&hT0, g_hT0);
    cudaGetSymbolAddress((void**)&hT1, g_hT1);
    cudaGetSymbolAddress((void**)&dh, g_dh);
    cudaGetSymbolAddress((void**)&dec, g_decout);

    const dim3 grid(16, 8);
    const long long LDT = 65536;  // [B,128,512] row (batch) stride

    // ---------------- encoder: 4 layers, 128 sequential steps each ----------
    for (int l = 0; l < 4; ++l) {
        const float* Wih = (l == 0) ? eWih0 : eWih + (long long)(l - 1) * 262144;
        const float* Whh = eWhh + (long long)l * 262144;
        const float* bi = ebih + l * 512;
        const float* bh = ebhh + l * 512;
        const float* src = (l == 1) ? bufA : (l == 2) ? bufB : bufA;  // l==3 -> bufA
        float* dst = (l == 0) ? bufA : (l == 1) ? bufB : (l == 2) ? bufA : enc_out;
        for (int t = 0; t < 128; ++t) {
            const float* X;
            long long ldx;
            int k1;
            if (l == 0) { X = x + (long long)t * 6; ldx = 768; k1 = 6; }
            else        { X = src + (long long)t * 512; ldx = LDT; k1 = 512; }
            const float* Hp = (t > 0) ? dst + (long long)(t - 1) * 512 : nullptr;
            float* o2 = nullptr;
            if (t == 127 && l == 0) o2 = hT0;
            if (t == 127 && l == 1) o2 = hT1;
            step_kernel<<<grid, 256>>>(X, ldx, k1, Wih, Hp, LDT, Whh, bi, bh,
                                       dst + (long long)t * 512, LDT, o2, 512);
        }
    }

    // ---------------- decoder: 10 steps x 4 layers --------------------------
    for (int s = 0; s < 10; ++s) {
        const int wset = s & 1;
        const int rset = (s - 1) & 1;
        for (int l = 0; l < 4; ++l) {
            const float* X;
            long long ldx;
            if (l == 0) {
                if (s == 0) { X = enc_out + 127LL * 512; ldx = LDT; }
                else        { X = dh + ((long long)rset * 4 + 3) * 524288; ldx = 512; }
            } else {
                X = dh + ((long long)wset * 4 + (l - 1)) * 524288;
                ldx = 512;
            }
            const float* Hp;
            long long ldh;
            if (s == 0) {
                if (l == 0)      { Hp = hT0; ldh = 512; }
                else if (l == 1) { Hp = hT1; ldh = 512; }
                else if (l == 2) { Hp = bufA + 127LL * 512; ldh = LDT; }
                else             { Hp = enc_out + 127LL * 512; ldh = LDT; }
            } else {
                Hp = dh + ((long long)rset * 4 + l) * 524288;
                ldh = 512;
            }
            float* o = dh + ((long long)wset * 4 + l) * 524288;
            float* o2 = (l == 3) ? dec + (long long)s * 512 : nullptr;
            step_kernel<<<grid, 256>>>(X, ldx, 512,
                                       dWih + (long long)l * 262144, Hp, ldh,
                                       dWhh + (long long)l * 262144,
                                       dbih + l * 512, dbhh + l * 512,
                                       o, 512, o2, 5120);
        }
    }

    // ---------------- FC head ----------------------------------------------
    fc_kernel<<<1280, 256>>>(dec, fcW, fcb, outputs);
}

// round 2
// speedup vs baseline: 3.3957x; 3.3957x over previous
#include <cuda_runtime.h>
#include <cuda_fp16.h>
#include <cstdint>

// ---------------------------------------------------------------------------
// Seq2Seq RNN (tanh), B=1024, T=128, H=512, L=4, PRED_LEN=10.
// Round 2: pre-split fp16 hi/lo weights (transposed, Wih;Whh fused K=1024),
// producer-side activation splitting, cp.async double-buffered mainloop,
// encoder anti-diagonal wavefront (131 launches, up to 512 CTAs each).
// ---------------------------------------------------------------------------

#define ACT_L 67108864LL  // halves per (layer, hi/lo) activation plane

// Scratch (device globals; allocation APIs are forbidden).
static __device__ __half g_act[8LL * ACT_L];     // [4 layers][2 hi/lo][1024*128*512]
static __device__ __half g_wenc_hi[2097152];     // [4][1024 k][512 n]
static __device__ __half g_wenc_lo[2097152];
static __device__ __half g_wdec_hi[2097152];
static __device__ __half g_wdec_lo[2097152];
static __device__ __half g_dh_hi[4194304];       // [2][4][1024][512] decoder ping-pong
static __device__ __half g_dh_lo[4194304];
static __device__ float  g_decout[5242880];      // [1024][10][512]

__device__ __forceinline__ uint32_t smem_u32(const void* p) {
    return (uint32_t)__cvta_generic_to_shared(p);
}

__device__ __forceinline__ void cp16(uint32_t saddr, const void* g) {
    asm volatile("cp.async.cg.shared.global [%0], [%1], 16;\n" :: "r"(saddr), "l"(g));
}

__device__ __forceinline__ void mma16816(float* c,
                                         uint32_t a0, uint32_t a1, uint32_t a2, uint32_t a3,
                                         uint32_t b0, uint32_t b1) {
    asm volatile(
        "mma.sync.aligned.m16n8k16.row.col.f32.f16.f16.f32 "
        "{%0,%1,%2,%3}, {%4,%5,%6,%7}, {%8,%9}, {%0,%1,%2,%3};"
        : "+f"(c[0]), "+f"(c[1]), "+f"(c[2]), "+f"(c[3])
        : "r"(a0), "r"(a1), "r"(a2), "r"(a3), "r"(b0), "r"(b1));
}

__device__ __forceinline__ void ldsm_x4(uint32_t addr, uint32_t& r0, uint32_t& r1,
                                        uint32_t& r2, uint32_t& r3) {
    asm volatile("ldmatrix.sync.aligned.m8n8.x4.shared.b16 {%0,%1,%2,%3}, [%4];"
                 : "=r"(r0), "=r"(r1), "=r"(r2), "=r"(r3) : "r"(addr));
}

__device__ __forceinline__ void ldsm_x4_t(uint32_t addr, uint32_t& r0, uint32_t& r1,
                                          uint32_t& r2, uint32_t& r3) {
    asm volatile("ldmatrix.sync.aligned.m8n8.x4.trans.shared.b16 {%0,%1,%2,%3}, [%4];"
                 : "=r"(r0), "=r"(r1), "=r"(r2), "=r"(r3) : "r"(addr));
}

struct __align__(16) Smem {
    __half A[2][2][64][40];   // [buf][hi/lo][m][k] pitch 40 (conflict-free ldsm)
    __half B[2][2][32][72];   // [buf][hi/lo][k][n] pitch 72
};

// out = tanh(X@Wih^T + H@Whh^T + bih + bhh), split-fp16 3-product GEMM.
// Weight rows [0,512) are the X part, [512,1024) the H part.
// kstart=512 -> no X GEMM (layer-0 raw input proj via Xraw), kend=512 -> no H.
__device__ __forceinline__ void step_core(
    Smem& sm,
    const __half* __restrict__ Xhi, const __half* __restrict__ Xlo, long long ldx,
    const __half* __restrict__ Hhi, const __half* __restrict__ Hlo, long long ldh,
    const __half* __restrict__ Whi, const __half* __restrict__ Wlo,
    const float* __restrict__ bih, const float* __restrict__ bhh,
    __half* __restrict__ outHi, __half* __restrict__ outLo, long long ldoh,
    float* __restrict__ out32, long long ldo32,
    int kstart, int kend,
    const float* __restrict__ Xraw, long long ldxraw, const float* __restrict__ Wih0)
{
    const int tid = threadIdx.x;
    const int lane = tid & 31;
    const int warp = tid >> 5;
    const int wm = (warp & 3) * 16;
    const int wn = (warp >> 2) * 32;
    const int bm0 = blockIdx.x * 64;
    const int bn0 = blockIdx.y * 64;

    float acc[4][4];
#pragma unroll
    for (int i = 0; i < 4; ++i)
#pragma unroll
        for (int j = 0; j < 4; ++j) acc[i][j] = 0.f;

    if (Xraw) {  // layer-0 tiny input projection (K=6), direct fp32
        const int mlo = bm0 + wm + (lane >> 2);
        float xr[2][6];
#pragma unroll
        for (int r = 0; r < 2; ++r)
#pragma unroll
            for (int k = 0; k < 6; ++k)
                xr[r][k] = Xraw[(long long)(mlo + r * 8) * ldxraw + k];
#pragma unroll
        for (int nt = 0; nt < 4; ++nt)
#pragma unroll
            for (int j = 0; j < 2; ++j) {
                const int gn = bn0 + wn + nt * 8 + (lane & 3) * 2 + j;
#pragma unroll
                for (int k = 0; k < 6; ++k) {
                    const float w = Wih0[gn * 6 + k];
                    acc[nt][j]     += xr[0][k] * w;
                    acc[nt][2 + j] += xr[1][k] * w;
                }
            }
    }

    const int nkb = (kend - kstart) >> 5;
    const int arow = tid >> 2, aq = (tid & 3) * 8;
    const int brow = tid >> 3, bq = (tid & 7) * 8;

    auto issue = [&](int kb) {
        const int k0 = kstart + kb * 32;
        const int buf = kb & 1;
        const __half *ah, *al;
        long long la;
        int kk;
        if (k0 < 512) { ah = Xhi; al = Xlo; la = ldx; kk = k0; }
        else          { ah = Hhi; al = Hlo; la = ldh; kk = k0 - 512; }
        const long long aoff = (long long)(bm0 + arow) * la + kk + aq;
        cp16(smem_u32(&sm.A[buf][0][arow][aq]), ah + aoff);
        cp16(smem_u32(&sm.A[buf][1][arow][aq]), al + aoff);
        const long long boff = (long long)(k0 + brow) * 512 + bn0 + bq;
        cp16(smem_u32(&sm.B[buf][0][brow][bq]), Whi + boff);
        cp16(smem_u32(&sm.B[buf][1][brow][bq]), Wlo + boff);
    };

    if (nkb > 0) {
        issue(0);
        asm volatile("cp.async.commit_group;\n" ::: "memory");
        for (int kb = 0; kb < nkb; ++kb) {
            if (kb + 1 < nkb) issue(kb + 1);
            asm volatile("cp.async.commit_group;\n" ::: "memory");
            asm volatile("cp.async.wait_group 1;\n" ::: "memory");
            __syncthreads();
            const int buf = kb & 1;
#pragma unroll
            for (int combo = 0; combo < 3; ++combo) {
                const __half (*Ap)[40] = (combo == 1) ? sm.A[buf][1] : sm.A[buf][0];
                const __half (*Bp)[72] = (combo == 2) ? sm.B[buf][1] : sm.B[buf][0];
#pragma unroll
                for (int kk = 0; kk < 32; kk += 16) {
                    uint32_t a0, a1, a2, a3;
                    const uint32_t aaddr =
                        smem_u32(&Ap[wm + (lane & 15)][kk + ((lane >> 4) << 3)]);
                    ldsm_x4(aaddr, a0, a1, a2, a3);
#pragma unroll
                    for (int pair = 0; pair < 2; ++pair) {
                        const int nb = wn + pair * 16;
                        const uint32_t baddr = smem_u32(
                            &Bp[kk + (lane & 7) + (((lane >> 3) & 1) << 3)]
                               [nb + ((lane >> 4) << 3)]);
                        uint32_t b0, b1, b2, b3;
                        ldsm_x4_t(baddr, b0, b1, b2, b3);
                        mma16816(acc[pair * 2 + 0], a0, a1, a2, a3, b0, b1);
                        mma16816(acc[pair * 2 + 1], a0, a1, a2, a3, b2, b3);
                    }
                }
            }
            __syncthreads();
        }
    }

    // epilogue: bias + tanh + producer-side split write (+ optional fp32 write)
#pragma unroll
    for (int nt = 0; nt < 4; ++nt)
#pragma unroll
        for (int i = 0; i < 2; ++i)
#pragma unroll
            for (int j = 0; j < 2; ++j) {
                const int m = bm0 + wm + (lane >> 2) + i * 8;
                const int gn = bn0 + wn + nt * 8 + (lane & 3) * 2 + j;
                const float v = tanhf(acc[nt][i * 2 + j] + bih[gn] + bhh[gn]);
                const __half hi = __float2half_rn(v);
                const __half lo = __float2half_rn(v - __half2float(hi));
                outHi[(long long)m * ldoh + gn] = hi;
                outLo[(long long)m * ldoh + gn] = lo;
                if (out32) out32[(long long)m * ldo32 + gn] = v;
            }
}

// Encoder wavefront: one kernel per anti-diagonal d = l + t. blockIdx.z picks
// the layer (offset by l_base); all (l, d-l) cells on a diagonal are independent.
__global__ void __launch_bounds__(256) enc_diag_kernel(
    int d, int l_base,
    const float* __restrict__ xraw, const float* __restrict__ Wih0,
    const float* __restrict__ ebih, const float* __restrict__ ebhh,
    float* __restrict__ enc_out)
{
    __shared__ Smem sm;
    const int l = l_base + blockIdx.z;
    const int t = d - l;

    const __half* Whi = g_wenc_hi + (long long)l * 524288;
    const __half* Wlo = g_wenc_lo + (long long)l * 524288;
    __half* actl_hi = g_act + ((long long)l * 2 + 0) * ACT_L;
    __half* actl_lo = g_act + ((long long)l * 2 + 1) * ACT_L;

    const __half *Xhi = nullptr, *Xlo = nullptr, *Hhi = nullptr, *Hlo = nullptr;
    long long ldx = 0;
    int kstart = 512, kend = 512;
    const float* Xr = nullptr;

    if (l == 0) {
        Xr = xraw + (long long)t * 6;
    } else {
        const __half* prev = g_act + ((long long)(l - 1) * 2) * ACT_L;
        Xhi = prev + (long long)t * 512;
        Xlo = prev + ACT_L + (long long)t * 512;
        ldx = 65536;
        kstart = 0;
    }
    if (t > 0) {
        Hhi = actl_hi + (long long)(t - 1) * 512;
        Hlo = actl_lo + (long long)(t - 1) * 512;
        kend = 1024;
    }
    float* o32 = (l == 3) ? enc_out + (long long)t * 512 : nullptr;

    step_core(sm, Xhi, Xlo, ldx, Hhi, Hlo, 65536,
              Whi, Wlo, ebih + l * 512, ebhh + l * 512,
              actl_hi + (long long)t * 512, actl_lo + (long long)t * 512, 65536,
              o32, 65536, kstart, kend, Xr, 768, Wih0);
}

__global__ void __launch_bounds__(256) dec_step_kernel(
    const __half* __restrict__ Xhi, const __half* __restrict__ Xlo, long long ldx,
    const __half* __restrict__ Hhi, const __half* __restrict__ Hlo, long long ldh,
    const __half* __restrict__ Whi, const __half* __restrict__ Wlo,
    const float* __restrict__ bih, const float* __restrict__ bhh,
    __half* __restrict__ outHi, __half* __restrict__ outLo,
    float* __restrict__ out32, long long ldo32)
{
    __shared__ Smem sm;
    step_core(sm, Xhi, Xlo, ldx, Hhi, Hlo, ldh, Whi, Wlo, bih, bhh,
              outHi, outLo, 512, out32, ldo32, 0, 1024, nullptr, 0, nullptr);
}

// Split + transpose all weights once: W[l][k][n], k<512 = Wih part, k>=512 = Whh.
__global__ void __launch_bounds__(256) prep_kernel(
    const float* __restrict__ eWih, const float* __restrict__ eWhh,
    const float* __restrict__ dWih, const float* __restrict__ dWhh)
{
    const long long idx = (long long)blockIdx.x * 256 + threadIdx.x;
    const long long total = 2097152;
    const int model = idx >= total;
    const long long j = idx - (long long)model * total;
    const int l = (int)(j >> 19);
    const int r = (int)((j >> 9) & 1023);
    const int n = (int)(j & 511);
    float v;
    if (!model) {
        if (r < 512) v = (l == 0) ? 0.f : eWih[(((long long)(l - 1) * 512 + n) << 9) + r];
        else         v = eWhh[(((long long)l * 512 + n) << 9) + (r - 512)];
    } else {
        if (r < 512) v = dWih[(((long long)l * 512 + n) << 9) + r];
        else         v = dWhh[(((long long)l * 512 + n) << 9) + (r - 512)];
    }
    const __half hi = __float2half_rn(v);
    const __half lo = __float2half_rn(v - __half2float(hi));
    if (!model) { g_wenc_hi[j] = hi; g_wenc_lo[j] = lo; }
    else        { g_wdec_hi[j] = hi; g_wdec_lo[j] = lo; }
}

// outputs[r, n] = decout[r, :] @ fcW[n, :] + fcb[n]
__global__ void __launch_bounds__(256) fc_kernel(
    const float* __restrict__ in, const float* __restrict__ W,
    const float* __restrict__ b, float* __restrict__ out)
{
    __shared__ float Ws[6 * 512];
    const int tid = threadIdx.x;
    for (int i = tid; i < 6 * 512; i += 256) Ws[i] = W[i];
    __syncthreads();

    const int warp = tid >> 5, lane = tid & 31;
    const int row = blockIdx.x * 8 + warp;
    float p[6] = {0.f, 0.f, 0.f, 0.f, 0.f, 0.f};
    for (int k = lane; k < 512; k += 32) {
        const float v = in[(long long)row * 512 + k];
#pragma unroll
        for (int n = 0; n < 6; ++n) p[n] += v * Ws[n * 512 + k];
    }
#pragma unroll
    for (int off = 16; off > 0; off >>= 1)
#pragma unroll
        for (int n = 0; n < 6; ++n)
            p[n] += __shfl_down_sync(0xffffffffu, p[n], off);
    if (lane == 0) {
#pragma unroll
        for (int n = 0; n < 6; ++n) out[(long long)row * 6 + n] = p[n] + b[n];
    }
}

extern "C" void kernel_launch(void* const* d_in, const int* in_sizes, int n_in,
                              void* d_out, int out_size) {
    const float* x     = (const float*)d_in[0];
    const float* eWih0 = (const float*)d_in[1];
    const float* eWih  = (const float*)d_in[2];
    const float* eWhh  = (const float*)d_in[3];
    const float* ebih  = (const float*)d_in[4];
    const float* ebhh  = (const float*)d_in[5];
    const float* dWih  = (const float*)d_in[6];
    const float* dWhh  = (const float*)d_in[7];
    const float* dbih  = (const float*)d_in[8];
    const float* dbhh  = (const float*)d_in[9];
    const float* fcW   = (const float*)d_in[10];
    const float* fcb   = (const float*)d_in[11];

    float* out = (float*)d_out;
    float* enc_out = out;               // [1024,128,512]
    float* outputs = out + 67108864LL;  // [1024,10,6]

    __half *actB, *dhHi, *dhLo, *wdHi, *wdLo;
    float* decout;
    cudaGetSymbolAddress((void**)&actB, g_act);
    cudaGetSymbolAddress((void**)&dhHi, g_dh_hi);
    cudaGetSymbolAddress((void**)&dhLo, g_dh_lo);
    cudaGetSymbolAddress((void**)&wdHi, g_wdec_hi);
    cudaGetSymbolAddress((void**)&wdLo, g_wdec_lo);
    cudaGetSymbolAddress((void**)&decout, g_decout);

    // 1) weight split/transpose
    prep_kernel<<<16384, 256>>>(eWih, eWhh, dWih, dWhh);

    // 2) encoder wavefront: 131 diagonals
    for (int d = 0; d < 131; ++d) {
        const int llo = (d > 127) ? d - 127 : 0;
        const int lhi = (d < 3) ? d : 3;
        dim3 grid(16, 8, lhi - llo + 1);
        enc_diag_kernel<<<grid, 256>>>(d, llo, x, eWih0, ebih, ebhh, enc_out);
    }

    // 3) decoder: 10 steps x 4 layers, serial (feedback forbids wavefront)
    const dim3 grid(16, 8);
    for (int s = 0; s < 10; ++s) {
        const int wset = s & 1;
        const int rset = (s - 1) & 1;
        for (int l = 0; l < 4; ++l) {
            const __half *Xhi, *Xlo, *Hhi, *Hlo;
            long long ldx, ldh;
            if (l == 0) {
                if (s == 0) {
                    Xhi = actB + 6 * ACT_L + 127LL * 512;
                    Xlo = actB + 7 * ACT_L + 127LL * 512;
                    ldx = 65536;
                } else {
                    Xhi = dhHi + ((long long)rset * 4 + 3) * 524288;
                    Xlo = dhLo + ((long long)rset * 4 + 3) * 524288;
                    ldx = 512;
                }
            } else {
                Xhi = dhHi + ((long long)wset * 4 + (l - 1)) * 524288;
                Xlo = dhLo + ((long long)wset * 4 + (l - 1)) * 524288;
                ldx = 512;
            }
            if (s == 0) {
                Hhi = actB + ((long long)l * 2 + 0) * ACT_L + 127LL * 512;
                Hlo = actB + ((long long)l * 2 + 1) * ACT_L + 127LL * 512;
                ldh = 65536;
            } else {
                Hhi = dhHi + ((long long)rset * 4 + l) * 524288;
                Hlo = dhLo + ((long long)rset * 4 + l) * 524288;
                ldh = 512;
            }
            __half* oHi = dhHi + ((long long)wset * 4 + l) * 524288;
            __half* oLo = dhLo + ((long long)wset * 4 + l) * 524288;
            float* o32 = (l == 3) ? decout + (long long)s * 512 : nullptr;
            dec_step_kernel<<<grid, 256>>>(
                Xhi, Xlo, ldx, Hhi, Hlo, ldh,
                wdHi + (long long)l * 524288, wdLo + (long long)l * 524288,
                dbih + l * 512, dbhh + l * 512, oHi, oLo, o32, 5120);
        }
    }

    // 4) FC head
    fc_kernel<<<1280, 256>>>(decout, fcW, fcb, outputs);
}